// round 13
// baseline (speedup 1.0000x reference)
#include <cuda_runtime.h>

// DFMB PS ROI Align for GB300. C=10, PH=PW=7 (P=49), H=W=34, S=4, N=16384.
//
// R13 strategy:
//  - transpose feature map to [p][y][x][c_pad16] (64B/position, contiguous x)
//  - separable 4x4 subsample bilinear -> per-bin wx[4], wy[4] window weights
//  - phase 1 (1 thread/bin): geometry ONCE, emit per-ROW entries
//    {wy*invc, rowbase, wx0..wx3} for rows with wy != 0 (avg ~2.7 of 4)
//  - phase 2 (4 lanes/bin = channel quads): per row load ALL 4 columns as
//    4 independent LDG.128 (256B contiguous, MLP=4, branch-free), then
//    4 FMUL + 16 FFMA. Zero-weight columns contribute exact zeros
//    (scratch pad region is never-written zero-initialized device global).

#define NC   10
#define CP   16        // padded channel stride (64B per position)
#define NPH  7
#define NPW  7
#define NP   49
#define NH   34
#define NW   34
#define NHW  1156
#define ROWSTRIDE (NW * CP)   // 544 floats

// +2048 pad: unconditional 4-column row loads can run past the valid region
// by up to ~1231 elements; pad is zero-init and never written -> reads 0.
__device__ float g_ft_t[NP * NHW * CP + 2048];

// ---------------------------------------------------------------------------
// Kernel 1: transpose [C][P][H*W] -> [P][H*W][CP], zero pad c>=10
// ---------------------------------------------------------------------------
__global__ __launch_bounds__(256) void transpose_kernel(const float* __restrict__ ft) {
    int idx = blockIdx.x * 256 + threadIdx.x;
    const int total = NP * NHW * CP;
    if (idx >= total) return;
    int c    = idx & (CP - 1);
    int rest = idx >> 4;
    int yx   = rest % NHW;
    int p    = rest / NHW;
    float v = 0.0f;
    if (c < NC) v = ft[(c * NP + p) * NHW + yx];
    g_ft_t[idx] = v;
}

// ---------------------------------------------------------------------------
// Kernel 2: main ROI align
// ---------------------------------------------------------------------------
__global__ __launch_bounds__(256) void roi_kernel(const float* __restrict__ rois,
                                                  float* __restrict__ out,
                                                  int nbins) {
    // per-bin row entries: e0 = {wy*invc, rowbase(bitcast), wx0, wx1},
    //                      e1 = {wx2, wx3}
    __shared__ float4 s_e0[256 * 4];     // 16 KB
    __shared__ float2 s_e1[256 * 4];     //  8 KB
    __shared__ int    s_nr[256];         //  1 KB
    __shared__ int    s_ob[256];         //  1 KB

    const int tid = threadIdx.x;
    const int bin = blockIdx.x * 256 + tid;

    // ---------------- Phase 1: per-bin geometry -> row entries ------------
    {
        int nrows = 0;
        int outb  = -1;

        if (bin < nbins) {
            int n  = bin / NP;
            int p  = bin - n * NP;
            int ph = p / NPW;
            int pw = p - ph * NPW;

            const float* r = rois + n * 5;
            float rsw = r[1] * 0.0625f;
            float rsh = r[2] * 0.0625f;
            float rew = r[3] * 0.0625f;
            float reh = r[4] * 0.0625f;

            float roi_h = reh - rsh; roi_h = (roi_h > 0.1f) ? roi_h : 0.1f;
            float roi_w = rew - rsw; roi_w = (roi_w > 0.1f) ? roi_w : 0.1f;
            float bin_h = roi_h / 7.0f;
            float bin_w = roi_w / 7.0f;
            float sub_h = bin_h * 0.25f;
            float sub_w = bin_w * 0.25f;

            // no FMA contraction: floor() boundary must match reference
            float hstart = floorf(__fadd_rn(rsh, __fmul_rn((float)ph, bin_h)));
            float wstart = floorf(__fadd_rn(rsw, __fmul_rn((float)pw, bin_w)));

            float wx0 = 0.f, wx1 = 0.f, wx2 = 0.f, wx3 = 0.f;
            float wy0 = 0.f, wy1 = 0.f, wy2 = 0.f, wy3 = 0.f;

            // ---- X direction ----
            float ckx = 0.0f;
            int ax = 0;
            #pragma unroll
            for (int j = 0; j < 4; j++) {
                float w   = __fadd_rn(wstart, __fmul_rn((float)j + 0.5f, sub_w));
                float x1f = floorf(w);
                float x2f = ceilf(w);
                int x1 = (int)x1f; x1 = max(0, min(NW - 1, x1));
                int x2 = (int)x2f; x2 = max(0, min(NW - 1, x2));
                if (j == 0) ax = x1;   // window origin; corners land in [ax, ax+3]
                float kx  = (w > -1.0f && w < (float)NW) ? 1.0f : 0.0f;
                float x1v = (x1f >= 0.0f && x1f < (float)NW) ? kx : 0.0f;
                float x2v = (x2f >= 0.0f && x2f < (float)NW) ? kx : 0.0f;
                float dx  = w - (float)x1;       // vs CLAMPED corner (ref semantics)
                float wa  = x1v * (1.0f - dx);
                float wb  = x2v * dx;
                int s1 = x1 - ax, s2 = x2 - ax;
                wx0 += (s1 == 0 ? wa : 0.f) + (s2 == 0 ? wb : 0.f);
                wx1 += (s1 == 1 ? wa : 0.f) + (s2 == 1 ? wb : 0.f);
                wx2 += (s1 == 2 ? wa : 0.f) + (s2 == 2 ? wb : 0.f);
                wx3 += (s1 == 3 ? wa : 0.f) + (s2 == 3 ? wb : 0.f);
                ckx += kx;
            }

            // ---- Y direction ----
            float cky = 0.0f;
            int by = 0;
            #pragma unroll
            for (int j = 0; j < 4; j++) {
                float h   = __fadd_rn(hstart, __fmul_rn((float)j + 0.5f, sub_h));
                float y1f = floorf(h);
                float y2f = ceilf(h);
                int y1 = (int)y1f; y1 = max(0, min(NH - 1, y1));
                int y2 = (int)y2f; y2 = max(0, min(NH - 1, y2));
                if (j == 0) by = y1;
                float ky  = (h > -1.0f && h < (float)NH) ? 1.0f : 0.0f;
                float y1v = (y1f >= 0.0f && y1f < (float)NH) ? ky : 0.0f;
                float y2v = (y2f >= 0.0f && y2f < (float)NH) ? ky : 0.0f;
                float dy  = h - (float)y1;
                float wa  = y1v * (1.0f - dy);
                float wb  = y2v * dy;
                int s1 = y1 - by, s2 = y2 - by;
                wy0 += (s1 == 0 ? wa : 0.f) + (s2 == 0 ? wb : 0.f);
                wy1 += (s1 == 1 ? wa : 0.f) + (s2 == 1 ? wb : 0.f);
                wy2 += (s1 == 2 ? wa : 0.f) + (s2 == 2 ? wb : 0.f);
                wy3 += (s1 == 3 ? wa : 0.f) + (s2 == 3 ? wb : 0.f);
                cky += ky;
            }

            float count = ckx * cky;
            float denom = (count > 0.0f) ? count : 1.0f;
            float invc  = 1.0f / denom;
            int   boff  = (p * NHW + by * NW + ax) * CP;
            outb        = n * (NC * NP) + p;

            float wys[4] = {wy0, wy1, wy2, wy3};
            #pragma unroll
            for (int rr = 0; rr < 4; rr++) {
                float wyr = wys[rr] * invc;
                if (wyr != 0.0f) {
                    s_e0[tid * 4 + nrows] = make_float4(
                        wyr, __int_as_float(boff + rr * ROWSTRIDE), wx0, wx1);
                    s_e1[tid * 4 + nrows] = make_float2(wx2, wx3);
                    nrows++;
                }
            }
        }
        s_nr[tid] = nrows;
        s_ob[tid] = outb;
    }
    __syncthreads();

    // ---------------- Phase 2: channel-quad row gather --------------------
    const int subc = tid & 3;           // channel quad: floats [4*subc, 4*subc+4)
    const int g    = tid >> 2;          // 0..63
    const float* src = g_ft_t + 4 * subc;

    #pragma unroll 1
    for (int i = 0; i < 4; i++) {
        const int slot = i * 64 + g;    // warp covers 8 CONSECUTIVE bins
        const int nr = s_nr[slot];
        float a0 = 0.f, a1 = 0.f, a2 = 0.f, a3 = 0.f;

        #pragma unroll 1
        for (int k = 0; k < nr; k++) {
            float4 e0 = s_e0[slot * 4 + k];     // LDS.128 (quad broadcast)
            float2 e1 = s_e1[slot * 4 + k];     // LDS.64
            const float* rp = src + __float_as_int(e0.y);
            // 4 independent LDG.128 over 256 contiguous bytes -> MLP=4
            float4 v0 = *(const float4*)(rp);
            float4 v1 = *(const float4*)(rp + CP);
            float4 v2 = *(const float4*)(rp + 2 * CP);
            float4 v3 = *(const float4*)(rp + 3 * CP);
            float wy = e0.x;
            float w0 = wy * e0.z;
            float w1 = wy * e0.w;
            float w2 = wy * e1.x;
            float w3 = wy * e1.y;
            a0 = fmaf(w0, v0.x, a0); a1 = fmaf(w0, v0.y, a1);
            a2 = fmaf(w0, v0.z, a2); a3 = fmaf(w0, v0.w, a3);
            a0 = fmaf(w1, v1.x, a0); a1 = fmaf(w1, v1.y, a1);
            a2 = fmaf(w1, v1.z, a2); a3 = fmaf(w1, v1.w, a3);
            a0 = fmaf(w2, v2.x, a0); a1 = fmaf(w2, v2.y, a1);
            a2 = fmaf(w2, v2.z, a2); a3 = fmaf(w2, v2.w, a3);
            a0 = fmaf(w3, v3.x, a0); a1 = fmaf(w3, v3.y, a1);
            a2 = fmaf(w3, v3.z, a2); a3 = fmaf(w3, v3.w, a3);
        }

        const int ob = s_ob[slot];
        if (ob >= 0 && subc < 3) {
            float* o = out + ob + subc * 4 * NP;
            o[0]  = a0;                        // c = 4*subc
            o[NP] = a1;                        // c = 4*subc+1
            if (subc < 2) {
                o[2 * NP] = a2;                // c = 4*subc+2
                o[3 * NP] = a3;                // c = 4*subc+3
            }
        }
    }
}

// ---------------------------------------------------------------------------
extern "C" void kernel_launch(void* const* d_in, const int* in_sizes, int n_in,
                              void* d_out, int out_size) {
    const float* ft   = (const float*)d_in[0];   // (1, 490, 34, 34)
    const float* rois = (const float*)d_in[1];   // (N, 5)
    float* out = (float*)d_out;                  // (N, 10, 49)

    int N = in_sizes[1] / 5;
    int nbins = N * NP;

    {
        const int total = NP * NHW * CP;
        transpose_kernel<<<(total + 255) / 256, 256>>>(ft);
    }
    {
        roi_kernel<<<(nbins + 255) / 256, 256>>>(rois, out, nbins);
    }
}

// round 14
// speedup vs baseline: 1.2752x; 1.2752x over previous
#include <cuda_runtime.h>

// DFMB PS ROI Align for GB300. C=10, PH=PW=7 (P=49), H=W=34, S=4, N=16384.
//
// R14 strategy (= R12 structure + MLP-4 unrolled gather):
//  - transpose feature map to [p][y][x][c_pad16]  (64B/position, aligned)
//  - separable 4x4 subsample bilinear -> per-bin 4x4 window weights
//  - phase 1 (1 thread/bin): geometry ONCE, emit compact list of
//    (weight*invc, element offset) for nonzero-weight positions (avg ~9/16)
//  - phase 2 (4 lanes/bin, lane = channel quad): gather loop manually
//    unrolled x4: 2x LDS.128 (two packed entries each) + 4 independent
//    LDG.128 front-batched by ptxas -> MLP=4 against the ~250cyc L2 hit
//    latency that bound R12. FMA order per accumulator preserved.

#define NC   10
#define CP   16        // padded channel stride (64B per position)
#define NPH  7
#define NPW  7
#define NP   49
#define NH   34
#define NW   34
#define NHW  1156
#define ROWSTRIDE (NW * CP)   // 544 floats

__device__ float g_ft_t[NP * NHW * CP];   // 3.63 MB scratch

// ---------------------------------------------------------------------------
// Kernel 1: transpose [C][P][H*W] -> [P][H*W][CP], zero pad c>=10
// ---------------------------------------------------------------------------
__global__ __launch_bounds__(256) void transpose_kernel(const float* __restrict__ ft) {
    int idx = blockIdx.x * 256 + threadIdx.x;
    const int total = NP * NHW * CP;
    if (idx >= total) return;
    int c    = idx & (CP - 1);
    int rest = idx >> 4;
    int yx   = rest % NHW;
    int p    = rest / NHW;
    float v = 0.0f;
    if (c < NC) v = ft[(c * NP + p) * NHW + yx];
    g_ft_t[idx] = v;
}

// ---------------------------------------------------------------------------
// Kernel 2: main ROI align
// ---------------------------------------------------------------------------
struct __align__(16) BinList {
    float2 e[16];        // .x = weight*invc, .y = int offset (bit-cast)
    int n;               // number of active entries
    int outb;            // n*490 + p, or -1
    int pad0, pad1;
};                        // 144 B stride (16B-aligned, bank-conflict friendly)

__global__ __launch_bounds__(256) void roi_kernel(const float* __restrict__ rois,
                                                  float* __restrict__ out,
                                                  int nbins) {
    __shared__ BinList sb[256];          // 36864 B
    const int tid = threadIdx.x;
    const int bin = blockIdx.x * 256 + tid;

    // ---------------- Phase 1: per-bin geometry -> compact list -----------
    {
        int nent = 0;
        int outb = -1;

        if (bin < nbins) {
            int n  = bin / NP;
            int p  = bin - n * NP;
            int ph = p / NPW;
            int pw = p - ph * NPW;

            const float* r = rois + n * 5;
            float rsw = r[1] * 0.0625f;
            float rsh = r[2] * 0.0625f;
            float rew = r[3] * 0.0625f;
            float reh = r[4] * 0.0625f;

            float roi_h = reh - rsh; roi_h = (roi_h > 0.1f) ? roi_h : 0.1f;
            float roi_w = rew - rsw; roi_w = (roi_w > 0.1f) ? roi_w : 0.1f;
            float bin_h = roi_h / 7.0f;
            float bin_w = roi_w / 7.0f;
            float sub_h = bin_h * 0.25f;
            float sub_w = bin_w * 0.25f;

            // no FMA contraction: floor() boundary must match reference
            float hstart = floorf(__fadd_rn(rsh, __fmul_rn((float)ph, bin_h)));
            float wstart = floorf(__fadd_rn(rsw, __fmul_rn((float)pw, bin_w)));

            float wx0 = 0.f, wx1 = 0.f, wx2 = 0.f, wx3 = 0.f;
            float wy0 = 0.f, wy1 = 0.f, wy2 = 0.f, wy3 = 0.f;

            // ---- X direction ----
            float ckx = 0.0f;
            int ax = 0;
            #pragma unroll
            for (int j = 0; j < 4; j++) {
                float w   = __fadd_rn(wstart, __fmul_rn((float)j + 0.5f, sub_w));
                float x1f = floorf(w);
                float x2f = ceilf(w);
                int x1 = (int)x1f; x1 = max(0, min(NW - 1, x1));
                int x2 = (int)x2f; x2 = max(0, min(NW - 1, x2));
                if (j == 0) ax = x1;   // window origin; corners land in [ax, ax+3]
                float kx  = (w > -1.0f && w < (float)NW) ? 1.0f : 0.0f;
                float x1v = (x1f >= 0.0f && x1f < (float)NW) ? kx : 0.0f;
                float x2v = (x2f >= 0.0f && x2f < (float)NW) ? kx : 0.0f;
                float dx  = w - (float)x1;       // vs CLAMPED corner (ref semantics)
                float wa  = x1v * (1.0f - dx);
                float wb  = x2v * dx;
                int s1 = x1 - ax, s2 = x2 - ax;
                wx0 += (s1 == 0 ? wa : 0.f) + (s2 == 0 ? wb : 0.f);
                wx1 += (s1 == 1 ? wa : 0.f) + (s2 == 1 ? wb : 0.f);
                wx2 += (s1 == 2 ? wa : 0.f) + (s2 == 2 ? wb : 0.f);
                wx3 += (s1 == 3 ? wa : 0.f) + (s2 == 3 ? wb : 0.f);
                ckx += kx;
            }

            // ---- Y direction ----
            float cky = 0.0f;
            int by = 0;
            #pragma unroll
            for (int j = 0; j < 4; j++) {
                float h   = __fadd_rn(hstart, __fmul_rn((float)j + 0.5f, sub_h));
                float y1f = floorf(h);
                float y2f = ceilf(h);
                int y1 = (int)y1f; y1 = max(0, min(NH - 1, y1));
                int y2 = (int)y2f; y2 = max(0, min(NH - 1, y2));
                if (j == 0) by = y1;
                float ky  = (h > -1.0f && h < (float)NH) ? 1.0f : 0.0f;
                float y1v = (y1f >= 0.0f && y1f < (float)NH) ? ky : 0.0f;
                float y2v = (y2f >= 0.0f && y2f < (float)NH) ? ky : 0.0f;
                float dy  = h - (float)y1;
                float wa  = y1v * (1.0f - dy);
                float wb  = y2v * dy;
                int s1 = y1 - by, s2 = y2 - by;
                wy0 += (s1 == 0 ? wa : 0.f) + (s2 == 0 ? wb : 0.f);
                wy1 += (s1 == 1 ? wa : 0.f) + (s2 == 1 ? wb : 0.f);
                wy2 += (s1 == 2 ? wa : 0.f) + (s2 == 2 ? wb : 0.f);
                wy3 += (s1 == 3 ? wa : 0.f) + (s2 == 3 ? wb : 0.f);
                cky += ky;
            }

            float count = ckx * cky;
            float denom = (count > 0.0f) ? count : 1.0f;
            float invc  = 1.0f / denom;
            int   boff  = (p * NHW + by * NW + ax) * CP;
            outb        = n * (NC * NP) + p;

            float wxs[4] = {wx0, wx1, wx2, wx3};
            float wys[4] = {wy0 * invc, wy1 * invc, wy2 * invc, wy3 * invc};

            #pragma unroll
            for (int rr = 0; rr < 4; rr++) {
                #pragma unroll
                for (int ss = 0; ss < 4; ss++) {
                    float wv = wys[rr] * wxs[ss];
                    if (wv != 0.0f) {
                        sb[tid].e[nent] = make_float2(
                            wv, __int_as_float(boff + rr * ROWSTRIDE + ss * CP));
                        nent++;
                    }
                }
            }
        }
        sb[tid].n = nent;
        sb[tid].outb = outb;
    }
    __syncthreads();

    // ---------------- Phase 2: channel-quad gather, unroll x4 -------------
    const int subc = tid & 3;           // channel quad: floats [4*subc, 4*subc+4)
    const int g    = tid >> 2;          // 0..63
    const float* src = g_ft_t + 4 * subc;

    #pragma unroll 1
    for (int i = 0; i < 4; i++) {
        const BinList& b = sb[i * 64 + g];   // warp covers 8 CONSECUTIVE bins
        const int n = b.n;
        float a0 = 0.f, a1 = 0.f, a2 = 0.f, a3 = 0.f;

        int k = 0;
        #pragma unroll 1
        for (; k + 4 <= n; k += 4) {
            // two packed entries per LDS.128 (16B-aligned: 144B stride, k%4==0)
            float4 p01 = *(const float4*)&b.e[k];       // w0,o0,w1,o1
            float4 p23 = *(const float4*)&b.e[k + 2];   // w2,o2,w3,o3
            // 4 independent LDG.128 -> MLP=4
            float4 v0 = *(const float4*)(src + __float_as_int(p01.y));
            float4 v1 = *(const float4*)(src + __float_as_int(p01.w));
            float4 v2 = *(const float4*)(src + __float_as_int(p23.y));
            float4 v3 = *(const float4*)(src + __float_as_int(p23.w));
            a0 = fmaf(p01.x, v0.x, a0); a1 = fmaf(p01.x, v0.y, a1);
            a2 = fmaf(p01.x, v0.z, a2); a3 = fmaf(p01.x, v0.w, a3);
            a0 = fmaf(p01.z, v1.x, a0); a1 = fmaf(p01.z, v1.y, a1);
            a2 = fmaf(p01.z, v1.z, a2); a3 = fmaf(p01.z, v1.w, a3);
            a0 = fmaf(p23.x, v2.x, a0); a1 = fmaf(p23.x, v2.y, a1);
            a2 = fmaf(p23.x, v2.z, a2); a3 = fmaf(p23.x, v2.w, a3);
            a0 = fmaf(p23.z, v3.x, a0); a1 = fmaf(p23.z, v3.y, a1);
            a2 = fmaf(p23.z, v3.z, a2); a3 = fmaf(p23.z, v3.w, a3);
        }
        #pragma unroll 1
        for (; k < n; k++) {
            float2 e = b.e[k];
            float4 v = *(const float4*)(src + __float_as_int(e.y));
            a0 = fmaf(e.x, v.x, a0); a1 = fmaf(e.x, v.y, a1);
            a2 = fmaf(e.x, v.z, a2); a3 = fmaf(e.x, v.w, a3);
        }

        const int ob = b.outb;
        if (ob >= 0 && subc < 3) {
            float* o = out + ob + subc * 4 * NP;
            o[0]  = a0;                        // c = 4*subc
            o[NP] = a1;                        // c = 4*subc+1
            if (subc < 2) {
                o[2 * NP] = a2;                // c = 4*subc+2
                o[3 * NP] = a3;                // c = 4*subc+3
            }
        }
    }
}

// ---------------------------------------------------------------------------
extern "C" void kernel_launch(void* const* d_in, const int* in_sizes, int n_in,
                              void* d_out, int out_size) {
    const float* ft   = (const float*)d_in[0];   // (1, 490, 34, 34)
    const float* rois = (const float*)d_in[1];   // (N, 5)
    float* out = (float*)d_out;                  // (N, 10, 49)

    int N = in_sizes[1] / 5;
    int nbins = N * NP;

    {
        const int total = NP * NHW * CP;
        transpose_kernel<<<(total + 255) / 256, 256>>>(ft);
    }
    {
        roi_kernel<<<(nbins + 255) / 256, 256>>>(rois, out, nbins);
    }
}

// round 15
// speedup vs baseline: 1.3788x; 1.0813x over previous
#include <cuda_runtime.h>

// DFMB PS ROI Align for GB300. C=10, PH=PW=7 (P=49), H=W=34, S=4, N=16384.
//
// R15 strategy (= R14 + software-pipelined gather):
//  - transpose feature map to [p][y][x][c_pad16]  (64B/position, aligned)
//  - separable 4x4 subsample bilinear -> per-bin 4x4 window weights
//  - phase 1 (1 thread/bin): geometry ONCE, compact list of
//    (weight*invc, element offset) for nonzero positions, PADDED with
//    zero-weight entries to a multiple of 4 (fmaf(0,x,a)==a exactly).
//  - phase 2 (4 lanes/bin = channel quad): fully unrolled 4-batch pipeline,
//    batch j+1's 4 independent LDG.128 issued BEFORE batch j's 16 FFMA
//    -> up to 8 loads in flight per warp, L2-hit latency hidden.

#define NC   10
#define CP   16        // padded channel stride (64B per position)
#define NPH  7
#define NPW  7
#define NP   49
#define NH   34
#define NW   34
#define NHW  1156
#define ROWSTRIDE (NW * CP)   // 544 floats

__device__ float g_ft_t[NP * NHW * CP];   // 3.63 MB scratch

// ---------------------------------------------------------------------------
// Kernel 1: transpose [C][P][H*W] -> [P][H*W][CP], zero pad c>=10
// ---------------------------------------------------------------------------
__global__ __launch_bounds__(256) void transpose_kernel(const float* __restrict__ ft) {
    int idx = blockIdx.x * 256 + threadIdx.x;
    const int total = NP * NHW * CP;
    if (idx >= total) return;
    int c    = idx & (CP - 1);
    int rest = idx >> 4;
    int yx   = rest % NHW;
    int p    = rest / NHW;
    float v = 0.0f;
    if (c < NC) v = ft[(c * NP + p) * NHW + yx];
    g_ft_t[idx] = v;
}

// ---------------------------------------------------------------------------
// Kernel 2: main ROI align
// ---------------------------------------------------------------------------
struct __align__(16) BinList {
    float2 e[16];        // .x = weight*invc, .y = int offset (bit-cast)
    int n;               // number of entries (multiple of 4 for active bins)
    int outb;            // n*490 + p, or -1
    int pad0, pad1;
};                        // 144 B stride

#define ACC4(ww, vv) \
    a0 = fmaf(ww, vv.x, a0); a1 = fmaf(ww, vv.y, a1); \
    a2 = fmaf(ww, vv.z, a2); a3 = fmaf(ww, vv.w, a3);

#define LOADB(eA, eB, vA, vB, vC, vD, idx) \
    eA = E[2*(idx)]; eB = E[2*(idx)+1]; \
    vA = *(const float4*)(src + __float_as_int(eA.y)); \
    vB = *(const float4*)(src + __float_as_int(eA.w)); \
    vC = *(const float4*)(src + __float_as_int(eB.y)); \
    vD = *(const float4*)(src + __float_as_int(eB.w));

#define FMAB(eA, eB, vA, vB, vC, vD) \
    ACC4(eA.x, vA) ACC4(eA.z, vB) ACC4(eB.x, vC) ACC4(eB.z, vD)

__global__ __launch_bounds__(256, 4) void roi_kernel(const float* __restrict__ rois,
                                                     float* __restrict__ out,
                                                     int nbins) {
    __shared__ BinList sb[256];          // 36864 B
    const int tid = threadIdx.x;
    const int bin = blockIdx.x * 256 + tid;

    // ---------------- Phase 1: per-bin geometry -> compact list -----------
    {
        int nent = 0;
        int outb = -1;

        if (bin < nbins) {
            int n  = bin / NP;
            int p  = bin - n * NP;
            int ph = p / NPW;
            int pw = p - ph * NPW;

            const float* r = rois + n * 5;
            float rsw = r[1] * 0.0625f;
            float rsh = r[2] * 0.0625f;
            float rew = r[3] * 0.0625f;
            float reh = r[4] * 0.0625f;

            float roi_h = reh - rsh; roi_h = (roi_h > 0.1f) ? roi_h : 0.1f;
            float roi_w = rew - rsw; roi_w = (roi_w > 0.1f) ? roi_w : 0.1f;
            float bin_h = roi_h / 7.0f;
            float bin_w = roi_w / 7.0f;
            float sub_h = bin_h * 0.25f;
            float sub_w = bin_w * 0.25f;

            // no FMA contraction: floor() boundary must match reference
            float hstart = floorf(__fadd_rn(rsh, __fmul_rn((float)ph, bin_h)));
            float wstart = floorf(__fadd_rn(rsw, __fmul_rn((float)pw, bin_w)));

            float wx0 = 0.f, wx1 = 0.f, wx2 = 0.f, wx3 = 0.f;
            float wy0 = 0.f, wy1 = 0.f, wy2 = 0.f, wy3 = 0.f;

            // ---- X direction ----
            float ckx = 0.0f;
            int ax = 0;
            #pragma unroll
            for (int j = 0; j < 4; j++) {
                float w   = __fadd_rn(wstart, __fmul_rn((float)j + 0.5f, sub_w));
                float x1f = floorf(w);
                float x2f = ceilf(w);
                int x1 = (int)x1f; x1 = max(0, min(NW - 1, x1));
                int x2 = (int)x2f; x2 = max(0, min(NW - 1, x2));
                if (j == 0) ax = x1;   // window origin; corners land in [ax, ax+3]
                float kx  = (w > -1.0f && w < (float)NW) ? 1.0f : 0.0f;
                float x1v = (x1f >= 0.0f && x1f < (float)NW) ? kx : 0.0f;
                float x2v = (x2f >= 0.0f && x2f < (float)NW) ? kx : 0.0f;
                float dx  = w - (float)x1;       // vs CLAMPED corner (ref semantics)
                float wa  = x1v * (1.0f - dx);
                float wb  = x2v * dx;
                int s1 = x1 - ax, s2 = x2 - ax;
                wx0 += (s1 == 0 ? wa : 0.f) + (s2 == 0 ? wb : 0.f);
                wx1 += (s1 == 1 ? wa : 0.f) + (s2 == 1 ? wb : 0.f);
                wx2 += (s1 == 2 ? wa : 0.f) + (s2 == 2 ? wb : 0.f);
                wx3 += (s1 == 3 ? wa : 0.f) + (s2 == 3 ? wb : 0.f);
                ckx += kx;
            }

            // ---- Y direction ----
            float cky = 0.0f;
            int by = 0;
            #pragma unroll
            for (int j = 0; j < 4; j++) {
                float h   = __fadd_rn(hstart, __fmul_rn((float)j + 0.5f, sub_h));
                float y1f = floorf(h);
                float y2f = ceilf(h);
                int y1 = (int)y1f; y1 = max(0, min(NH - 1, y1));
                int y2 = (int)y2f; y2 = max(0, min(NH - 1, y2));
                if (j == 0) by = y1;
                float ky  = (h > -1.0f && h < (float)NH) ? 1.0f : 0.0f;
                float y1v = (y1f >= 0.0f && y1f < (float)NH) ? ky : 0.0f;
                float y2v = (y2f >= 0.0f && y2f < (float)NH) ? ky : 0.0f;
                float dy  = h - (float)y1;
                float wa  = y1v * (1.0f - dy);
                float wb  = y2v * dy;
                int s1 = y1 - by, s2 = y2 - by;
                wy0 += (s1 == 0 ? wa : 0.f) + (s2 == 0 ? wb : 0.f);
                wy1 += (s1 == 1 ? wa : 0.f) + (s2 == 1 ? wb : 0.f);
                wy2 += (s1 == 2 ? wa : 0.f) + (s2 == 2 ? wb : 0.f);
                wy3 += (s1 == 3 ? wa : 0.f) + (s2 == 3 ? wb : 0.f);
                cky += ky;
            }

            float count = ckx * cky;
            float denom = (count > 0.0f) ? count : 1.0f;
            float invc  = 1.0f / denom;
            int   boff  = (p * NHW + by * NW + ax) * CP;
            outb        = n * (NC * NP) + p;

            float wxs[4] = {wx0, wx1, wx2, wx3};
            float wys[4] = {wy0 * invc, wy1 * invc, wy2 * invc, wy3 * invc};

            #pragma unroll
            for (int rr = 0; rr < 4; rr++) {
                #pragma unroll
                for (int ss = 0; ss < 4; ss++) {
                    float wv = wys[rr] * wxs[ss];
                    if (wv != 0.0f) {
                        sb[tid].e[nent] = make_float2(
                            wv, __int_as_float(boff + rr * ROWSTRIDE + ss * CP));
                        nent++;
                    }
                }
            }
            // pad to multiple of 4 with exact-zero entries (offset 0 is valid)
            while (nent & 3) {
                sb[tid].e[nent] = make_float2(0.0f, __int_as_float(0));
                nent++;
            }
        }
        sb[tid].n = nent;
        sb[tid].outb = outb;
    }
    __syncthreads();

    // ---------------- Phase 2: pipelined channel-quad gather --------------
    const int subc = tid & 3;           // channel quad: floats [4*subc, 4*subc+4)
    const int g    = tid >> 2;          // 0..63
    const float* src = g_ft_t + 4 * subc;

    #pragma unroll 1
    for (int i = 0; i < 4; i++) {
        const BinList& b = sb[i * 64 + g];   // warp covers 8 CONSECUTIVE bins
        const int iters = b.n >> 2;          // 0..4
        const float4* E = (const float4*)b.e;
        float a0 = 0.f, a1 = 0.f, a2 = 0.f, a3 = 0.f;

        if (iters > 0) {
            float4 e0, e1, e2, e3, e4, e5, e6, e7;
            float4 v0, v1, v2, v3, v4, v5, v6, v7;
            float4 v8, v9, va, vb, vc, vd, ve, vf;
            LOADB(e0, e1, v0, v1, v2, v3, 0)
            if (iters > 1) {
                LOADB(e2, e3, v4, v5, v6, v7, 1)
                FMAB(e0, e1, v0, v1, v2, v3)
                if (iters > 2) {
                    LOADB(e4, e5, v8, v9, va, vb, 2)
                    FMAB(e2, e3, v4, v5, v6, v7)
                    if (iters > 3) {
                        LOADB(e6, e7, vc, vd, ve, vf, 3)
                        FMAB(e4, e5, v8, v9, va, vb)
                        FMAB(e6, e7, vc, vd, ve, vf)
                    } else {
                        FMAB(e4, e5, v8, v9, va, vb)
                    }
                } else {
                    FMAB(e2, e3, v4, v5, v6, v7)
                }
            } else {
                FMAB(e0, e1, v0, v1, v2, v3)
            }
        }

        const int ob = b.outb;
        if (ob >= 0 && subc < 3) {
            float* o = out + ob + subc * 4 * NP;
            o[0]  = a0;                        // c = 4*subc
            o[NP] = a1;                        // c = 4*subc+1
            if (subc < 2) {
                o[2 * NP] = a2;                // c = 4*subc+2
                o[3 * NP] = a3;                // c = 4*subc+3
            }
        }
    }
}

// ---------------------------------------------------------------------------
extern "C" void kernel_launch(void* const* d_in, const int* in_sizes, int n_in,
                              void* d_out, int out_size) {
    const float* ft   = (const float*)d_in[0];   // (1, 490, 34, 34)
    const float* rois = (const float*)d_in[1];   // (N, 5)
    float* out = (float*)d_out;                  // (N, 10, 49)

    int N = in_sizes[1] / 5;
    int nbins = N * NP;

    {
        const int total = NP * NHW * CP;
        transpose_kernel<<<(total + 255) / 256, 256>>>(ft);
    }
    {
        roi_kernel<<<(nbins + 255) / 256, 256>>>(rois, out, nbins);
    }
}